// round 8
// baseline (speedup 1.0000x reference)
#include <cuda_runtime.h>
#include <cstdint>
#include <cstddef>

#define BB 256
#define SS 512
#define IN 512
#define HH 1024
#define OUTD 3
#define BH (BB*HH)
#define XROW ((size_t)SS*IN)
#define NCH 48
#define NKT 192
#define WBLK (NKT*4*32)            // float2 per block slab = 24576 (192KB)
#define NSLOT2 (128*WBLK)          // 3145728 float2 = 25MB
#define AOFF (WBLK*2)              // word offset of A-frag region = 49152
#define SMEMW (AOFF + 8192)        // 57344 words
#define SMEMB (SMEMW*4)            // 229376 bytes <= 232448 opt-in

__device__ float g_r[4*BH];
__device__ float g_h[BH];
__device__ float g_c[BH];
__device__ float2 g_wpack[NSLOT2];
__device__ unsigned g_bar_count, g_bar_sense;

__device__ __forceinline__ float sigf(float x){ return 1.f/(1.f+expf(-x)); }
__device__ __forceinline__ uint32_t f2tf(float f){
    uint32_t r; asm("cvt.rna.tf32.f32 %0,%1;":"=r"(r):"f"(f)); return r;
}

__device__ __forceinline__ void gridbar(unsigned& ls){
    ls ^= 1u; __threadfence(); __syncthreads();
    if (threadIdx.x == 0) {
        unsigned v = atomicAdd(&g_bar_count,1u);
        if (v == 127u) { atomicExch(&g_bar_count,0u); atomicExch(&g_bar_sense,ls); }
        else { while (*(volatile unsigned*)&g_bar_sense != ls) {} }
        __threadfence();
    }
    __syncthreads();
}

__device__ __forceinline__ void out_proj_warp(
    int b,int sidx,const float*__restrict__ Wout,const float*__restrict__ bout,
    float*__restrict__ out)
{
    const int lane = threadIdx.x & 31;
    float a0=0.f,a1=0.f,a2=0.f;
    const float* hrow = g_h + (size_t)b*HH;
#pragma unroll 8
    for (int j=0;j<HH/32;j++){
        float hv = hrow[lane+32*j];
        const float* wr = Wout + (size_t)(lane+32*j)*OUTD;
        a0=fmaf(hv,wr[0],a0); a1=fmaf(hv,wr[1],a1); a2=fmaf(hv,wr[2],a2);
    }
#pragma unroll
    for (int off=16;off;off>>=1){
        a0 += __shfl_down_sync(0xffffffffu,a0,off);
        a1 += __shfl_down_sync(0xffffffffu,a1,off);
        a2 += __shfl_down_sync(0xffffffffu,a2,off);
    }
    if (lane==0){
        float s0=a0+bout[0], s1=a1+bout[1], s2=a2+bout[2];
        float m=fmaxf(s0,fmaxf(s1,s2));
        float e0=expf(s0-m), e1=expf(s1-m), e2=expf(s2-m);
        float inv=1.f/(e0+e1+e2);
        size_t ob=((size_t)b*SS+sidx)*OUTD;
        out[ob]=e0*inv; out[ob+1]=e1*inv; out[ob+2]=e2*inv;
    }
}

// pack: slab per (gate,grp): [ktile 192][nt 4][lane 32] -> (B[k][n], B[k+4][n]) tf32
__global__ __launch_bounds__(256) void pack_w(
    const float*__restrict__ Whi,const float*__restrict__ Whf,
    const float*__restrict__ Whg,const float*__restrict__ Who,
    const float*__restrict__ Wxi,const float*__restrict__ Wxf,
    const float*__restrict__ Wxg,const float*__restrict__ Wxo)
{
    for (int slot = blockIdx.x*256+threadIdx.x; slot < NSLOT2; slot += gridDim.x*256){
        int lane = slot&31, t = slot>>5;
        int nt = t&3; t >>= 2;
        int ktile = t%NKT; t /= NKT;
        int grp = t&31;
        int gate = t>>5;
        const float* Wh = (gate==0)?Whi:(gate==1)?Whf:(gate==2)?Whg:Who;
        const float* Wx = (gate==0)?Wxi:(gate==1)?Wxf:(gate==2)?Wxg:Wxo;
        const float* W; int k;
        if (ktile<128){ W=Wh; k=ktile*8+(lane&3); }
        else          { W=Wx; k=(ktile-128)*8+(lane&3); }
        int n = grp*32 + nt*8 + (lane>>2);
        float2 v;
        v.x = __uint_as_float(f2tf(W[(size_t)k*HH+n]));
        v.y = __uint_as_float(f2tf(W[(size_t)(k+4)*HH+n]));
        g_wpack[slot] = v;
    }
}

// weight-stationary persistent tf32-MMA: 128 blocks x 256 thr, 1 blk/SM.
// block = (gate=blk>>5, grp=blk&31): cols [grp*32,+32) of gate, M=256, K=1536.
// warp w: m-tiles {2w, 2w+1}; all 4 n-tiles.
__global__ __launch_bounds__(256,1) void lstm_mma(
    const float*__restrict__ x,
    const float*__restrict__ h0,const float*__restrict__ c0,
    const float*__restrict__ bi,const float*__restrict__ bf,
    const float*__restrict__ bg,const float*__restrict__ bo,
    const float*__restrict__ Wout,const float*__restrict__ bout,
    float*__restrict__ out,int write_hc)
{
    extern __shared__ uint32_t smU[];
    const int tid=threadIdx.x, blk=blockIdx.x;
    const int gate=blk>>5, grp=blk&31;
    const int n0=grp*32;
    const int w=tid>>5, lane=tid&31;
    const float* bias=(gate==0)?bi:(gate==1)?bf:(gate==2)?bg:bo;
    float* rg = g_r + (size_t)gate*BH;

    // load this block's weight slab into smem (once per launch)
    {
        const float4* src = (const float4*)(g_wpack + (size_t)(gate*32+grp)*WBLK);
        float4* dst = (float4*)smU;
#pragma unroll
        for (int i=0;i<48;i++) dst[tid+256*i] = src[tid+256*i];
    }

    float2 bias_r[4];
#pragma unroll
    for (int nt=0;nt<4;nt++)
        bias_r[nt] = *(const float2*)&bias[n0 + nt*8 + 2*(lane&3)];

    __syncthreads();
    unsigned ls=0;

    for (int s=0;s<SS;s++){
        if (s>0 && w<2) out_proj_warp(blk*2+w, s-1, Wout, bout, out);

        float acc[2][4][4];
#pragma unroll
        for (int mi=0;mi<2;mi++)
#pragma unroll
            for (int nt=0;nt<4;nt++)
#pragma unroll
                for (int q=0;q<4;q++) acc[mi][nt][q]=0.f;

        for (int ch=0;ch<NCH;ch++){
            const float* asrc; size_t arow;
            if (ch<32){ asrc=((s==0)?h0:g_h)+ch*32; arow=HH; }
            else      { asrc=x+(size_t)s*IN+(ch-32)*32; arow=XROW; }
            __syncthreads();    // prior MMA reads of A done
            // stage A chunk (256 m x 32 k) into frag layout [mt][kt][reg][lane]
#pragma unroll
            for (int i=0;i<8;i++){
                int f = tid + 256*i;          // 2048 float4s
                int m = f>>3, c4 = f&7;
                float4 v = *(const float4*)&asrc[(size_t)m*arow + c4*4];
                uint4 u;
                u.x=f2tf(v.x); u.y=f2tf(v.y); u.z=f2tf(v.z); u.w=f2tf(v.w);
                int mt=m>>4, r=m&15, kt=c4>>1, reg=(r>>3)+2*(c4&1);
                *(uint4*)&smU[AOFF + (((mt*4+kt)*4+reg)<<5) + ((r&7)<<2)] = u;
            }
            __syncthreads();
#pragma unroll
            for (int kt=0;kt<4;kt++){
                uint32_t a[2][4];
#pragma unroll
                for (int mi=0;mi<2;mi++){
                    int base = AOFF + ((((w*2+mi)*4+kt)*4)<<5) + lane;
                    a[mi][0]=smU[base]; a[mi][1]=smU[base+32];
                    a[mi][2]=smU[base+64]; a[mi][3]=smU[base+96];
                }
                int ktile = ch*4+kt;
#pragma unroll
                for (int nt=0;nt<4;nt++){
                    float2 b = *(const float2*)&smU[((ktile*4+nt)*32+lane)*2];
                    uint32_t bx=__float_as_uint(b.x), by=__float_as_uint(b.y);
#pragma unroll
                    for (int mi=0;mi<2;mi++){
                        asm volatile(
                            "mma.sync.aligned.m16n8k8.row.col.f32.tf32.tf32.f32 "
                            "{%0,%1,%2,%3},{%4,%5,%6,%7},{%8,%9},{%0,%1,%2,%3};"
                            : "+f"(acc[mi][nt][0]),"+f"(acc[mi][nt][1]),
                              "+f"(acc[mi][nt][2]),"+f"(acc[mi][nt][3])
                            : "r"(a[mi][0]),"r"(a[mi][1]),"r"(a[mi][2]),"r"(a[mi][3]),
                              "r"(bx),"r"(by));
                    }
                }
            }
        }
        // epilogue: +bias -> g_r (rows w*32..w*32+31, cols n0..n0+31)
#pragma unroll
        for (int mi=0;mi<2;mi++){
            int r0 = (w*2+mi)*16 + (lane>>2);
#pragma unroll
            for (int nt=0;nt<4;nt++){
                int n = n0 + nt*8 + 2*(lane&3);
                float2 v0, v1;
                v0.x=acc[mi][nt][0]+bias_r[nt].x; v0.y=acc[mi][nt][1]+bias_r[nt].y;
                v1.x=acc[mi][nt][2]+bias_r[nt].x; v1.y=acc[mi][nt][3]+bias_r[nt].y;
                *(float2*)&rg[(size_t)r0*HH+n] = v0;
                *(float2*)&rg[(size_t)(r0+8)*HH+n] = v1;
            }
        }

        gridbar(ls);

        // phase 2: gates -> c,h (2048 contiguous elems per block)
        {
            size_t e0 = (size_t)blk*2048 + (size_t)tid*8;
#pragma unroll
            for (int v=0;v<2;v++){
                size_t e = e0 + (size_t)v*4;
                float4 ri =*(const float4*)&g_r[e];
                float4 rf =*(const float4*)&g_r[BH+e];
                float4 rg4=*(const float4*)&g_r[2*BH+e];
                float4 ro =*(const float4*)&g_r[3*BH+e];
                float4 cv = (s==0)?*(const float4*)&c0[e]:*(const float4*)&g_c[e];
                float4 cn,hn;
                { float iv=sigf(ri.x),fv=sigf(rf.x),gv=tanhf(rg4.x),ov=sigf(ro.x);
                  cn.x=fv*cv.x+iv*gv; hn.x=ov*tanhf(cn.x); }
                { float iv=sigf(ri.y),fv=sigf(rf.y),gv=tanhf(rg4.y),ov=sigf(ro.y);
                  cn.y=fv*cv.y+iv*gv; hn.y=ov*tanhf(cn.y); }
                { float iv=sigf(ri.z),fv=sigf(rf.z),gv=tanhf(rg4.z),ov=sigf(ro.z);
                  cn.z=fv*cv.z+iv*gv; hn.z=ov*tanhf(cn.z); }
                { float iv=sigf(ri.w),fv=sigf(rf.w),gv=tanhf(rg4.w),ov=sigf(ro.w);
                  cn.w=fv*cv.w+iv*gv; hn.w=ov*tanhf(cn.w); }
                *(float4*)&g_c[e]=cn; *(float4*)&g_h[e]=hn;
            }
        }

        gridbar(ls);   // 1024 barriers/launch -> even, replay-safe
    }

    if (w<2) out_proj_warp(blk*2+w, SS-1, Wout, bout, out);

    if (write_hc){
        float* oh = out + (size_t)BB*SS*OUTD;
        float* oc = oh + BH;
        size_t e0 = (size_t)blk*2048 + (size_t)tid*8;
#pragma unroll
        for (int v=0;v<2;v++){
            size_t e = e0 + (size_t)v*4;
            *(float4*)&oh[e] = *(const float4*)&g_h[e];
            *(float4*)&oc[e] = *(const float4*)&g_c[e];
        }
    }
}

extern "C" void kernel_launch(void* const* d_in, const int* in_sizes, int n_in,
                              void* d_out, int out_size)
{
    const float* x   =(const float*)d_in[0];
    const float* h0  =(const float*)d_in[1];
    const float* c0  =(const float*)d_in[2];
    const float* Xi  =(const float*)d_in[3];
    const float* Hi  =(const float*)d_in[4];
    const float* bi  =(const float*)d_in[5];
    const float* Xf  =(const float*)d_in[6];
    const float* Hf  =(const float*)d_in[7];
    const float* bf  =(const float*)d_in[8];
    const float* Xg  =(const float*)d_in[9];
    const float* Hg  =(const float*)d_in[10];
    const float* bg  =(const float*)d_in[11];
    const float* Xo  =(const float*)d_in[12];
    const float* Ho  =(const float*)d_in[13];
    const float* bo  =(const float*)d_in[14];
    const float* Wout=(const float*)d_in[15];
    const float* bout=(const float*)d_in[16];
    float* out=(float*)d_out;
    const int write_hc = (out_size >= BB*SS*OUTD + 2*BH) ? 1 : 0;

    cudaFuncSetAttribute(lstm_mma, cudaFuncAttributeMaxDynamicSharedMemorySize, SMEMB);
    pack_w<<<3072,256>>>(Hi,Hf,Hg,Ho,Xi,Xf,Xg,Xo);
    lstm_mma<<<128,256,SMEMB>>>(x,h0,c0,bi,bf,bg,bo,Wout,bout,out,write_hc);
}

// round 10
// speedup vs baseline: 2.2376x; 2.2376x over previous
#include <cuda_runtime.h>
#include <cstdint>
#include <cstddef>

#define BB 256
#define SS 512
#define IN 512
#define HH 1024
#define OUTD 3
#define BH (BB*HH)
#define XROW ((size_t)SS*IN)
#define NCH 48
#define NSLOT (4*8*NCH*4*16*32)
// smem words: B double buf 2*4096, A double buf 2*2304 at offset 8192
#define AOFFW 8192
#define SMEMB 51200

__device__ float g_r[4*BH];
__device__ float g_h[BH];
__device__ float g_c[BH];
__device__ float2 g_wpack[NSLOT];     // tf32 B-fragment order (R7 layout)
__device__ unsigned g_bar_count, g_bar_sense;

__device__ __forceinline__ float sigf(float x){ return 1.f/(1.f+expf(-x)); }
__device__ __forceinline__ uint32_t f2tf(float f){
    uint32_t r; asm("cvt.rna.tf32.f32 %0,%1;":"=r"(r):"f"(f)); return r;
}

__device__ __forceinline__ void gridbar(unsigned& ls){
    ls ^= 1u; __threadfence(); __syncthreads();
    if (threadIdx.x == 0) {
        unsigned v = atomicAdd(&g_bar_count,1u);
        if (v == 127u) { atomicExch(&g_bar_count,0u); atomicExch(&g_bar_sense,ls); }
        else { while (*(volatile unsigned*)&g_bar_sense != ls) {} }
        __threadfence();
    }
    __syncthreads();
}

__device__ __forceinline__ void out_proj_warp(
    int b,int sidx,const float*__restrict__ Wout,const float*__restrict__ bout,
    float*__restrict__ out)
{
    const int lane = threadIdx.x & 31;
    float a0=0.f,a1=0.f,a2=0.f;
    const float* hrow = g_h + (size_t)b*HH;
#pragma unroll 8
    for (int j=0;j<HH/32;j++){
        float hv = hrow[lane+32*j];
        const float* wr = Wout + (size_t)(lane+32*j)*OUTD;
        a0=fmaf(hv,wr[0],a0); a1=fmaf(hv,wr[1],a1); a2=fmaf(hv,wr[2],a2);
    }
#pragma unroll
    for (int off=16;off;off>>=1){
        a0 += __shfl_down_sync(0xffffffffu,a0,off);
        a1 += __shfl_down_sync(0xffffffffu,a1,off);
        a2 += __shfl_down_sync(0xffffffffu,a2,off);
    }
    if (lane==0){
        float s0=a0+bout[0], s1=a1+bout[1], s2=a2+bout[2];
        float m=fmaxf(s0,fmaxf(s1,s2));
        float e0=expf(s0-m), e1=expf(s1-m), e2=expf(s2-m);
        float inv=1.f/(e0+e1+e2);
        size_t ob=((size_t)b*SS+sidx)*OUTD;
        out[ob]=e0*inv; out[ob+1]=e1*inv; out[ob+2]=e2*inv;
    }
}

// pack (identical to round-7 passing version): [gate][ntb][ch][kt][nt][lane]
__global__ __launch_bounds__(256) void pack_w(
    const float*__restrict__ Whi,const float*__restrict__ Whf,
    const float*__restrict__ Whg,const float*__restrict__ Who,
    const float*__restrict__ Wxi,const float*__restrict__ Wxf,
    const float*__restrict__ Wxg,const float*__restrict__ Wxo)
{
    for (int slot = blockIdx.x*256+threadIdx.x; slot < NSLOT; slot += gridDim.x*256){
        int lane = slot&31, t = slot>>5;
        int nt = t&15; t >>= 4;
        int kt = t&3;  t >>= 2;
        int ch = t%NCH; t /= NCH;
        int ntb = t&7;
        int gate = t>>3;
        const float* Wh = (gate==0)?Whi:(gate==1)?Whf:(gate==2)?Whg:Who;
        const float* Wx = (gate==0)?Wxi:(gate==1)?Wxf:(gate==2)?Wxg:Wxo;
        const float* W; int kb;
        if (ch<32){ W=Wh; kb=ch*32; } else { W=Wx; kb=(ch-32)*32; }
        int k = kb + kt*8 + (lane&3);
        int n = ntb*128 + nt*8 + (lane>>2);
        float2 v;
        v.x = __uint_as_float(f2tf(W[(size_t)k*HH+n]));
        v.y = __uint_as_float(f2tf(W[(size_t)(k+4)*HH+n]));
        g_wpack[slot] = v;
    }
}

__device__ __forceinline__ void cpB(uint32_t sbase, int buf, const float2* wpB,
                                    int ch, int tid)
{
    const float4* src = (const float4*)(wpB + (size_t)ch*2048);
    uint32_t d0 = sbase + (uint32_t)(buf*4096 + tid*4)*4u;
    asm volatile("cp.async.cg.shared.global [%0],[%1],16;\n"::"r"(d0),"l"(src+tid));
    asm volatile("cp.async.cg.shared.global [%0],[%1],16;\n"::"r"(d0+8192u),"l"(src+tid+512));
    asm volatile("cp.async.commit_group;\n");
}

// pipelined tf32-MMA persistent kernel: 128 blocks x 512 thr, 1 blk/SM.
// block: gate=blk>>5, mtile=(blk>>3)&3 (m0, 64 rows), ntile=blk&7 (n0, 128 cols).
// warp w: mt=w>>2 (16 rows), nq=w&3 (4 n-tiles of 8 cols).
__global__ __launch_bounds__(512,1) void lstm_mma(
    const float*__restrict__ x,
    const float*__restrict__ h0,const float*__restrict__ c0,
    const float*__restrict__ bi,const float*__restrict__ bf,
    const float*__restrict__ bg,const float*__restrict__ bo,
    const float*__restrict__ Wout,const float*__restrict__ bout,
    float*__restrict__ out,int write_hc)
{
    extern __shared__ uint32_t smU[];
    const int tid=threadIdx.x, blk=blockIdx.x;
    const int gate=blk>>5, mtile=(blk>>3)&3, ntile=blk&7;
    const int m0=mtile*64, n0=ntile*128;
    const int w=tid>>5, lane=tid&31;
    const int mt=w>>2, nq=w&3;
    const float* bias=(gate==0)?bi:(gate==1)?bf:(gate==2)?bg:bo;
    float* rg = g_r + (size_t)gate*BH;
    const float2* wpB = g_wpack + (size_t)(gate*8+ntile)*NCH*2048;
    const int mrow = mt*16 + (lane>>2);
    const int am = tid>>3, ac = (tid&7)*4;     // A staging role: row, col
    uint32_t sbase = (uint32_t)__cvta_generic_to_shared(smU);

    float2 bias_r[4];
#pragma unroll
    for (int j=0;j<4;j++)
        bias_r[j] = *(const float2*)&bias[n0 + (nq*4+j)*8 + 2*(lane&3)];

    unsigned ls=0;

    for (int s=0;s<SS;s++){
        if (s>0 && w<2) out_proj_warp(blk*2+w, s-1, Wout, bout, out);

        const float* hbase = (s==0)?h0:g_h;
        float acc[4][4];
#pragma unroll
        for (int j=0;j<4;j++){ acc[j][0]=acc[j][1]=acc[j][2]=acc[j][3]=0.f; }

        // prologue: prefetch B0, stage A0
        cpB(sbase, 0, wpB, 0, tid);
        {
            float4 v = *(const float4*)&hbase[(size_t)(m0+am)*HH + ac];
            uint4 u; u.x=f2tf(v.x); u.y=f2tf(v.y); u.z=f2tf(v.z); u.w=f2tf(v.w);
            *(uint4*)&smU[AOFFW + am*36 + ac] = u;
        }
        asm volatile("cp.async.wait_group 0;\n");
        __syncthreads();

        for (int ch=0;ch<NCH;ch++){
            float4 v;
            const bool more = (ch+1 < NCH);
            if (more){
                cpB(sbase, (ch+1)&1, wpB, ch+1, tid);
                int c1 = ch+1;
                const float* asrc; size_t arow;
                if (c1<32){ asrc=hbase+c1*32; arow=HH; }
                else      { asrc=x+(size_t)s*IN+(c1-32)*32; arow=XROW; }
                v = *(const float4*)&asrc[(size_t)(m0+am)*arow + ac];
            }
            // MMA on buffers ch&1
            {
                const int ab = AOFFW + (ch&1)*2304;
                const int bb = (ch&1)*4096;
#pragma unroll
                for (int kt=0;kt<4;kt++){
                    int kcl = kt*8 + (lane&3);
                    uint32_t a0=smU[ab+mrow*36+kcl];
                    uint32_t a1=smU[ab+(mrow+8)*36+kcl];
                    uint32_t a2=smU[ab+mrow*36+kcl+4];
                    uint32_t a3=smU[ab+(mrow+8)*36+kcl+4];
#pragma unroll
                    for (int j=0;j<4;j++){
                        float2 b = *(const float2*)&smU[bb + ((kt*16 + nq*4 + j)*32 + lane)*2];
                        asm volatile(
                            "mma.sync.aligned.m16n8k8.row.col.f32.tf32.tf32.f32 "
                            "{%0,%1,%2,%3},{%4,%5,%6,%7},{%8,%9},{%0,%1,%2,%3};"
                            : "+f"(acc[j][0]),"+f"(acc[j][1]),"+f"(acc[j][2]),"+f"(acc[j][3])
                            : "r"(a0),"r"(a1),"r"(a2),"r"(a3),
                              "r"(__float_as_uint(b.x)),"r"(__float_as_uint(b.y)));
                    }
                }
            }
            if (more){
                uint4 u; u.x=f2tf(v.x); u.y=f2tf(v.y); u.z=f2tf(v.z); u.w=f2tf(v.w);
                *(uint4*)&smU[AOFFW + ((ch+1)&1)*2304 + am*36 + ac] = u;
            }
            asm volatile("cp.async.wait_group 0;\n");
            __syncthreads();
        }

        // epilogue: +bias -> g_r (warp tile: rows mt*16, cols nq*32)
        {
            int r0 = m0 + mrow;
#pragma unroll
            for (int j=0;j<4;j++){
                int n = n0 + (nq*4+j)*8 + 2*(lane&3);
                float2 v0, v1;
                v0.x=acc[j][0]+bias_r[j].x; v0.y=acc[j][1]+bias_r[j].y;
                v1.x=acc[j][2]+bias_r[j].x; v1.y=acc[j][3]+bias_r[j].y;
                *(float2*)&rg[(size_t)r0*HH+n] = v0;
                *(float2*)&rg[(size_t)(r0+8)*HH+n] = v1;
            }
        }

        gridbar(ls);

        // phase 2: gates -> c,h (2048 elems per block, 1 float4/thread)
        {
            size_t e = (size_t)blk*2048 + (size_t)tid*4;
            float4 ri =*(const float4*)&g_r[e];
            float4 rf =*(const float4*)&g_r[BH+e];
            float4 rg4=*(const float4*)&g_r[2*BH+e];
            float4 ro =*(const float4*)&g_r[3*BH+e];
            float4 cv = (s==0)?*(const float4*)&c0[e]:*(const float4*)&g_c[e];
            float4 cn,hn;
            { float iv=sigf(ri.x),fv=sigf(rf.x),gv=tanhf(rg4.x),ov=sigf(ro.x);
              cn.x=fv*cv.x+iv*gv; hn.x=ov*tanhf(cn.x); }
            { float iv=sigf(ri.y),fv=sigf(rf.y),gv=tanhf(rg4.y),ov=sigf(ro.y);
              cn.y=fv*cv.y+iv*gv; hn.y=ov*tanhf(cn.y); }
            { float iv=sigf(ri.z),fv=sigf(rf.z),gv=tanhf(rg4.z),ov=sigf(ro.z);
              cn.z=fv*cv.z+iv*gv; hn.z=ov*tanhf(cn.z); }
            { float iv=sigf(ri.w),fv=sigf(rf.w),gv=tanhf(rg4.w),ov=sigf(ro.w);
              cn.w=fv*cv.w+iv*gv; hn.w=ov*tanhf(cn.w); }
            *(float4*)&g_c[e]=cn; *(float4*)&g_h[e]=hn;
        }

        gridbar(ls);   // 1024 barriers/launch -> even, replay-safe
    }

    if (w<2) out_proj_warp(blk*2+w, SS-1, Wout, bout, out);

    if (write_hc){
        float* oh = out + (size_t)BB*SS*OUTD;
        float* oc = oh + BH;
        size_t e = (size_t)blk*2048 + (size_t)tid*4;
        *(float4*)&oh[e] = *(const float4*)&g_h[e];
        *(float4*)&oc[e] = *(const float4*)&g_c[e];
    }
}

extern "C" void kernel_launch(void* const* d_in, const int* in_sizes, int n_in,
                              void* d_out, int out_size)
{
    const float* x   =(const float*)d_in[0];
    const float* h0  =(const float*)d_in[1];
    const float* c0  =(const float*)d_in[2];
    const float* Xi  =(const float*)d_in[3];
    const float* Hi  =(const float*)d_in[4];
    const float* bi  =(const float*)d_in[5];
    const float* Xf  =(const float*)d_in[6];
    const float* Hf  =(const float*)d_in[7];
    const float* bf  =(const float*)d_in[8];
    const float* Xg  =(const float*)d_in[9];
    const float* Hg  =(const float*)d_in[10];
    const float* bg  =(const float*)d_in[11];
    const float* Xo  =(const float*)d_in[12];
    const float* Ho  =(const float*)d_in[13];
    const float* bo  =(const float*)d_in[14];
    const float* Wout=(const float*)d_in[15];
    const float* bout=(const float*)d_in[16];
    float* out=(float*)d_out;
    const int write_hc = (out_size >= BB*SS*OUTD + 2*BH) ? 1 : 0;

    cudaFuncSetAttribute(lstm_mma, cudaFuncAttributeMaxDynamicSharedMemorySize, SMEMB);
    pack_w<<<3072,256>>>(Hi,Hf,Hg,Ho,Xi,Xf,Xg,Xo);
    lstm_mma<<<128,512,SMEMB>>>(x,h0,c0,bi,bf,bg,bo,Wout,bout,out,write_hc);
}

// round 11
// speedup vs baseline: 3.1581x; 1.4114x over previous
#include <cuda_runtime.h>
#include <cstdint>
#include <cstddef>

#define BB 256
#define SS 512
#define IN 512
#define HH 1024
#define OUTD 3
#define BH (BB*HH)
#define XROW ((size_t)SS*IN)
#define NIT 24
#define NSLOT (32*48*4*4*4*32)
// smem words: B[2buf][2kg][4096] | A[2buf][2kg][2304] | merge[8192]
#define AOFF 16384
#define MOFF (AOFF + 4*2304)
#define SMEMW (MOFF + 8192)
#define SMEMB (SMEMW*4)

__device__ float g_hbuf[2][BH];
__device__ float g_c_unused;   // c lives in registers now
__device__ float2 g_wpack[NSLOT];
__device__ unsigned g_bar_count, g_bar_sense;

__device__ __forceinline__ float sigf(float x){ return 1.f/(1.f+expf(-x)); }
__device__ __forceinline__ uint32_t f2tf(float f){
    uint32_t r; asm("cvt.rna.tf32.f32 %0,%1;":"=r"(r):"f"(f)); return r;
}

__device__ __forceinline__ void gridbar(unsigned& ls){
    ls ^= 1u; __threadfence(); __syncthreads();
    if (threadIdx.x == 0) {
        unsigned v = atomicAdd(&g_bar_count,1u);
        if (v == 127u) { atomicExch(&g_bar_count,0u); atomicExch(&g_bar_sense,ls); }
        else { while (*(volatile unsigned*)&g_bar_sense != ls) {} }
        __threadfence();
    }
    __syncthreads();
}

__device__ __forceinline__ void out_proj_warp(
    const float* hbase, int b, int sidx,
    const float*__restrict__ Wout, const float*__restrict__ bout,
    float*__restrict__ out)
{
    const int lane = threadIdx.x & 31;
    float a0=0.f,a1=0.f,a2=0.f;
    const float* hrow = hbase + (size_t)b*HH;
#pragma unroll 8
    for (int j=0;j<HH/32;j++){
        float hv = hrow[lane+32*j];
        const float* wr = Wout + (size_t)(lane+32*j)*OUTD;
        a0=fmaf(hv,wr[0],a0); a1=fmaf(hv,wr[1],a1); a2=fmaf(hv,wr[2],a2);
    }
#pragma unroll
    for (int off=16;off;off>>=1){
        a0 += __shfl_down_sync(0xffffffffu,a0,off);
        a1 += __shfl_down_sync(0xffffffffu,a1,off);
        a2 += __shfl_down_sync(0xffffffffu,a2,off);
    }
    if (lane==0){
        float s0=a0+bout[0], s1=a1+bout[1], s2=a2+bout[2];
        float m=fmaxf(s0,fmaxf(s1,s2));
        float e0=expf(s0-m), e1=expf(s1-m), e2=expf(s2-m);
        float inv=1.f/(e0+e1+e2);
        size_t ob=((size_t)b*SS+sidx)*OUTD;
        out[ob]=e0*inv; out[ob+1]=e1*inv; out[ob+2]=e2*inv;
    }
}

// pack: slab per grp: [grp][ch 48][kt 4][ho 4][gate 4][lane 32] -> (W[k][n], W[k+4][n]) tf32
__global__ __launch_bounds__(256) void pack_w(
    const float*__restrict__ Whi,const float*__restrict__ Whf,
    const float*__restrict__ Whg,const float*__restrict__ Who,
    const float*__restrict__ Wxi,const float*__restrict__ Wxf,
    const float*__restrict__ Wxg,const float*__restrict__ Wxo)
{
    for (int slot = blockIdx.x*256+threadIdx.x; slot < NSLOT; slot += gridDim.x*256){
        int lane = slot&31, t = slot>>5;
        int gate = t&3; t >>= 2;
        int ho = t&3; t >>= 2;
        int kt = t&3; t >>= 2;
        int ch = t%48; int grp = t/48;
        const float* Wh = (gate==0)?Whi:(gate==1)?Whf:(gate==2)?Whg:Who;
        const float* Wx = (gate==0)?Wxi:(gate==1)?Wxf:(gate==2)?Wxg:Wxo;
        const float* W; int kb;
        if (ch<32){ W=Wh; kb=ch*32; } else { W=Wx; kb=(ch-32)*32; }
        int k = kb + kt*8 + (lane&3);
        int n = grp*32 + ho*8 + (lane>>2);
        float2 v;
        v.x = __uint_as_float(f2tf(W[(size_t)k*HH+n]));
        v.y = __uint_as_float(f2tf(W[(size_t)(k+4)*HH+n]));
        g_wpack[slot] = v;
    }
}

#define CPA16(d, s) asm volatile("cp.async.cg.shared.global [%0],[%1],16;\n"::"r"(d),"l"(s))

__device__ __forceinline__ void cpB2(uint32_t sbase, int buf, const float4* slab,
                                     int c0_, int c1_, int tid)
{
    uint32_t d0 = sbase + (uint32_t)((buf*2+0)*4096 + tid*4)*4u;
    uint32_t d1 = sbase + (uint32_t)((buf*2+1)*4096 + tid*4)*4u;
    const float4* s0 = slab + (size_t)c0_*1024;
    const float4* s1 = slab + (size_t)c1_*1024;
    CPA16(d0, s0+tid); CPA16(d0+8192u, s0+tid+512);
    CPA16(d1, s1+tid); CPA16(d1+8192u, s1+tid+512);
    asm volatile("cp.async.commit_group;\n");
}

__device__ __forceinline__ const float* chunk_src(int c, const float* hbase,
                                                  const float* x, int s, size_t* arow)
{
    if (c<32){ *arow = HH; return hbase + c*32; }
    *arow = XROW; return x + (size_t)s*IN + (c-32)*32;
}

// gate-fused K-split persistent tf32-MMA: 128 blocks x 512 thr, 1 blk/SM.
// block: mtile=blk>>5 (64 batch rows), grp=blk&31 (32 h-cols), ALL 4 gates.
// warp: kg=w>>3 (K half), wi=w&7: mt=wi>>2 (32 rows), ho=wi&3 (8 h-cols x 4 gates).
__global__ __launch_bounds__(512,1) void lstm_mma(
    const float*__restrict__ x,
    const float*__restrict__ h0,const float*__restrict__ c0,
    const float*__restrict__ bi,const float*__restrict__ bf,
    const float*__restrict__ bg,const float*__restrict__ bo,
    const float*__restrict__ Wout,const float*__restrict__ bout,
    float*__restrict__ out,int write_hc)
{
    extern __shared__ uint32_t smU[];
    float* smF = (float*)smU;
    const int tid=threadIdx.x, blk=blockIdx.x;
    const int mtile=blk>>5, grp=blk&31;
    const int m0=mtile*64;
    const int w=tid>>5, lane=tid&31;
    const int kg=w>>3, wi=w&7, mt=wi>>2, ho=wi&3;
    const int am=tid>>3, ac=(tid&7)*4;
    const int hcol0 = grp*32 + ho*8 + 2*(lane&3);
    uint32_t sbase = (uint32_t)__cvta_generic_to_shared(smU);
    const float4* slabF4 = (const float4*)(g_wpack + (size_t)grp*48*2048);

    float2 bias_r[4];
    bias_r[0] = *(const float2*)&bi[hcol0];
    bias_r[1] = *(const float2*)&bf[hcol0];
    bias_r[2] = *(const float2*)&bg[hcol0];
    bias_r[3] = *(const float2*)&bo[hcol0];

    float creg[8];
    unsigned ls=0;

    for (int s=0;s<SS;s++){
        const float* hbase = (s==0)?h0:g_hbuf[s&1];
        float* hnext = g_hbuf[(s+1)&1];

        if (s>0 && w<2) out_proj_warp(g_hbuf[s&1], blk*2+w, s-1, Wout, bout, out);

        float acc[2][4][4];
#pragma unroll
        for (int ms=0;ms<2;ms++)
#pragma unroll
            for (int g4=0;g4<4;g4++)
#pragma unroll
                for (int q=0;q<4;q++) acc[ms][g4][q]=0.f;

        // prologue: stage pair 0 (chunks 0 and 24) into buf 0
        cpB2(sbase, 0, slabF4, 0, NIT, tid);
#pragma unroll
        for (int kgc=0;kgc<2;kgc++){
            size_t ar; const float* src = chunk_src(kgc*NIT, hbase, x, s, &ar);
            float4 v = *(const float4*)&src[(size_t)(m0+am)*ar + ac];
            uint4 u; u.x=f2tf(v.x); u.y=f2tf(v.y); u.z=f2tf(v.z); u.w=f2tf(v.w);
            *(uint4*)&smU[AOFF + kgc*2304 + am*36 + ac] = u;
        }
        asm volatile("cp.async.wait_group 0;\n");
        __syncthreads();

        for (int i=0;i<NIT;i++){
            float4 va, vb;
            const bool more = (i+1 < NIT);
            if (more){
                cpB2(sbase, (i+1)&1, slabF4, i+1, NIT+i+1, tid);
                size_t ar0, ar1;
                const float* s0 = chunk_src(i+1, hbase, x, s, &ar0);
                const float* s1 = chunk_src(NIT+i+1, hbase, x, s, &ar1);
                va = *(const float4*)&s0[(size_t)(m0+am)*ar0 + ac];
                vb = *(const float4*)&s1[(size_t)(m0+am)*ar1 + ac];
            }
            // MMA on buf i&1, this warp's K-half chunk
            {
                const int abase = AOFF + ((i&1)*2+kg)*2304;
                const int bbase = ((i&1)*2+kg)*4096;
#pragma unroll
                for (int kt=0;kt<4;kt++){
                    int kcl = kt*8 + (lane&3);
                    uint32_t a[2][4];
#pragma unroll
                    for (int ms=0;ms<2;ms++){
                        int rb = abase + (mt*32+ms*16+(lane>>2))*36 + kcl;
                        a[ms][0]=smU[rb]; a[ms][1]=smU[rb+8*36];
                        a[ms][2]=smU[rb+4]; a[ms][3]=smU[rb+8*36+4];
                    }
#pragma unroll
                    for (int g4=0;g4<4;g4++){
                        float2 b = *(const float2*)&smU[bbase + ((kt*16+ho*4+g4)*32+lane)*2];
                        uint32_t bx=__float_as_uint(b.x), by=__float_as_uint(b.y);
#pragma unroll
                        for (int ms=0;ms<2;ms++){
                            asm volatile(
                                "mma.sync.aligned.m16n8k8.row.col.f32.tf32.tf32.f32 "
                                "{%0,%1,%2,%3},{%4,%5,%6,%7},{%8,%9},{%0,%1,%2,%3};"
                                : "+f"(acc[ms][g4][0]),"+f"(acc[ms][g4][1]),
                                  "+f"(acc[ms][g4][2]),"+f"(acc[ms][g4][3])
                                : "r"(a[ms][0]),"r"(a[ms][1]),"r"(a[ms][2]),"r"(a[ms][3]),
                                  "r"(bx),"r"(by));
                        }
                    }
                }
            }
            if (more){
                uint4 u;
                u.x=f2tf(va.x); u.y=f2tf(va.y); u.z=f2tf(va.z); u.w=f2tf(va.w);
                *(uint4*)&smU[AOFF + (((i+1)&1)*2+0)*2304 + am*36 + ac] = u;
                u.x=f2tf(vb.x); u.y=f2tf(vb.y); u.z=f2tf(vb.z); u.w=f2tf(vb.w);
                *(uint4*)&smU[AOFF + (((i+1)&1)*2+1)*2304 + am*36 + ac] = u;
            }
            asm volatile("cp.async.wait_group 0;\n");
            __syncthreads();
        }

        // K-split merge: kg1 -> smem (lane-major, conflict-free), kg0 adds
        if (kg==1){
            int hid = wi*32+lane;
#pragma unroll
            for (int ms=0;ms<2;ms++)
#pragma unroll
                for (int g4=0;g4<4;g4++)
#pragma unroll
                    for (int q=0;q<4;q++)
                        smF[MOFF + (((ms*4+g4)*4+q)<<8) + hid] = acc[ms][g4][q];
        }
        __syncthreads();

        // epilogue (kg0): add halves + bias, LSTM update with c in registers
        if (kg==0){
            int hid = wi*32+lane;
#pragma unroll
            for (int ms=0;ms<2;ms++){
#pragma unroll
                for (int hh=0;hh<2;hh++){
                    int m = m0 + mt*32 + ms*16 + (lane>>2) + hh*8;
                    int ci = (ms*2+hh)*2;
                    float2 hv;
#pragma unroll
                    for (int cc=0;cc<2;cc++){
                        int q = hh*2+cc;
                        float pi = acc[ms][0][q] + smF[MOFF + (((ms*4+0)*4+q)<<8) + hid]
                                 + ((cc==0)?bias_r[0].x:bias_r[0].y);
                        float pf = acc[ms][1][q] + smF[MOFF + (((ms*4+1)*4+q)<<8) + hid]
                                 + ((cc==0)?bias_r[1].x:bias_r[1].y);
                        float pg = acc[ms][2][q] + smF[MOFF + (((ms*4+2)*4+q)<<8) + hid]
                                 + ((cc==0)?bias_r[2].x:bias_r[2].y);
                        float po = acc[ms][3][q] + smF[MOFF + (((ms*4+3)*4+q)<<8) + hid]
                                 + ((cc==0)?bias_r[3].x:bias_r[3].y);
                        float iv=sigf(pi), fv=sigf(pf), gv=tanhf(pg), ov=sigf(po);
                        float cp = (s==0)? c0[(size_t)m*HH + hcol0 + cc] : creg[ci+cc];
                        float cn = fv*cp + iv*gv;
                        creg[ci+cc] = cn;
                        float hn = ov*tanhf(cn);
                        if (cc==0) hv.x = hn; else hv.y = hn;
                    }
                    *(float2*)&hnext[(size_t)m*HH + hcol0] = hv;
                    if (s==SS-1 && write_hc){
                        float* oh = out + (size_t)BB*SS*OUTD;
                        float* oc = oh + BH;
                        *(float2*)&oh[(size_t)m*HH + hcol0] = hv;
                        float2 cv2; cv2.x=creg[ci]; cv2.y=creg[ci+1];
                        *(float2*)&oc[(size_t)m*HH + hcol0] = cv2;
                    }
                }
            }
        }

        gridbar(ls);   // 512 gridbars/launch -> even, replay-safe
    }

    // final out-projection for s = SS-1 (h in g_hbuf[0] after last barrier)
    if (w<2) out_proj_warp(g_hbuf[SS&1], blk*2+w, SS-1, Wout, bout, out);
}

extern "C" void kernel_launch(void* const* d_in, const int* in_sizes, int n_in,
                              void* d_out, int out_size)
{
    const float* x   =(const float*)d_in[0];
    const float* h0  =(const float*)d_in[1];
    const float* c0  =(const float*)d_in[2];
    const float* Xi  =(const float*)d_in[3];
    const float* Hi  =(const float*)d_in[4];
    const float* bi  =(const float*)d_in[5];
    const float* Xf  =(const float*)d_in[6];
    const float* Hf  =(const float*)d_in[7];
    const float* bf  =(const float*)d_in[8];
    const float* Xg  =(const float*)d_in[9];
    const float* Hg  =(const float*)d_in[10];
    const float* bg  =(const float*)d_in[11];
    const float* Xo  =(const float*)d_in[12];
    const float* Ho  =(const float*)d_in[13];
    const float* bo  =(const float*)d_in[14];
    const float* Wout=(const float*)d_in[15];
    const float* bout=(const float*)d_in[16];
    float* out=(float*)d_out;
    const int write_hc = (out_size >= BB*SS*OUTD + 2*BH) ? 1 : 0;

    cudaFuncSetAttribute(lstm_mma, cudaFuncAttributeMaxDynamicSharedMemorySize, SMEMB);
    pack_w<<<3072,256>>>(Hi,Hf,Hg,Ho,Xi,Xf,Xg,Xo);
    lstm_mma<<<128,512,SMEMB>>>(x,h0,c0,bi,bf,bg,bo,Wout,bout,out,write_hc);
}

// round 13
// speedup vs baseline: 4.1204x; 1.3047x over previous
#include <cuda_runtime.h>
#include <cuda_fp16.h>
#include <cstdint>
#include <cstddef>

#define BB 256
#define SS 512
#define IN 512
#define HH 1024
#define OUTD 3
#define BH (BB*HH)
#define XROW ((size_t)SS*IN)
#define NIT 24
#define NSLOT (32*48*1024)
// smem words: B[2buf][2kg][2048] | A[2buf][2kg][1024] | merge[8192]
#define AOFFW 8192
#define MOFF (AOFFW + 4096)
#define SMEMW (MOFF + 8192)
#define SMEMB (SMEMW*4)

__device__ float g_hbuf[2][BH];
__device__ uint2 g_wpack[NSLOT];      // 12.6MB fp16 B-fragment order
__device__ unsigned g_bar_count, g_bar_sense;

__device__ __forceinline__ float sigf(float x){ return 1.f/(1.f+expf(-x)); }
__device__ __forceinline__ uint32_t pkh2(float lo, float hi){
    __half2 h = __floats2half2_rn(lo, hi);
    return *(uint32_t*)&h;
}

__device__ __forceinline__ void gridbar(unsigned& ls){
    ls ^= 1u; __threadfence(); __syncthreads();
    if (threadIdx.x == 0) {
        unsigned v = atomicAdd(&g_bar_count,1u);
        if (v == 127u) { atomicExch(&g_bar_count,0u); atomicExch(&g_bar_sense,ls); }
        else { while (*(volatile unsigned*)&g_bar_sense != ls) {} }
        __threadfence();
    }
    __syncthreads();
}

__device__ __forceinline__ void out_proj_warp(
    const float* hbase, int b, int sidx,
    const float*__restrict__ Wout, const float*__restrict__ bout,
    float*__restrict__ out)
{
    const int lane = threadIdx.x & 31;
    float a0=0.f,a1=0.f,a2=0.f;
    const float* hrow = hbase + (size_t)b*HH;
#pragma unroll 8
    for (int j=0;j<HH/32;j++){
        float hv = hrow[lane+32*j];
        const float* wr = Wout + (size_t)(lane+32*j)*OUTD;
        a0=fmaf(hv,wr[0],a0); a1=fmaf(hv,wr[1],a1); a2=fmaf(hv,wr[2],a2);
    }
#pragma unroll
    for (int off=16;off;off>>=1){
        a0 += __shfl_down_sync(0xffffffffu,a0,off);
        a1 += __shfl_down_sync(0xffffffffu,a1,off);
        a2 += __shfl_down_sync(0xffffffffu,a2,off);
    }
    if (lane==0){
        float s0=a0+bout[0], s1=a1+bout[1], s2=a2+bout[2];
        float m=fmaxf(s0,fmaxf(s1,s2));
        float e0=expf(s0-m), e1=expf(s1-m), e2=expf(s2-m);
        float inv=1.f/(e0+e1+e2);
        size_t ob=((size_t)b*SS+sidx)*OUTD;
        out[ob]=e0*inv; out[ob+1]=e1*inv; out[ob+2]=e2*inv;
    }
}

// pack fp16: per grp slab, per chunk 1024 uint2: [kt 2][ho 4][gate 4][lane 32]
// lane: b0={W[k0][n],W[k0+1][n]}, b1={W[k0+8][n],W[k0+9][n]}, k0=kb+kt*16+2*(lane&3)
__global__ __launch_bounds__(256) void pack_w(
    const float*__restrict__ Whi,const float*__restrict__ Whf,
    const float*__restrict__ Whg,const float*__restrict__ Who,
    const float*__restrict__ Wxi,const float*__restrict__ Wxf,
    const float*__restrict__ Wxg,const float*__restrict__ Wxo)
{
    for (int slot = blockIdx.x*256+threadIdx.x; slot < NSLOT; slot += gridDim.x*256){
        int lane = slot&31, t = slot>>5;
        int g4 = t&3; t >>= 2;
        int ho = t&3; t >>= 2;
        int kt = t&1; t >>= 1;
        int ch = t%48; int grp = t/48;
        const float* Wh = (g4==0)?Whi:(g4==1)?Whf:(g4==2)?Whg:Who;
        const float* Wx = (g4==0)?Wxi:(g4==1)?Wxf:(g4==2)?Wxg:Wxo;
        const float* W; int kb;
        if (ch<32){ W=Wh; kb=ch*32; } else { W=Wx; kb=(ch-32)*32; }
        int k0 = kb + kt*16 + 2*(lane&3);
        int n = grp*32 + ho*8 + (lane>>2);
        uint2 v;
        v.x = pkh2(W[(size_t)k0*HH+n],     W[(size_t)(k0+1)*HH+n]);
        v.y = pkh2(W[(size_t)(k0+8)*HH+n], W[(size_t)(k0+9)*HH+n]);
        g_wpack[slot] = v;
    }
}

#define CPA16(d, s) asm volatile("cp.async.cg.shared.global [%0],[%1],16;\n"::"r"(d),"l"(s))

__device__ __forceinline__ void cpB2(uint32_t sbase, int buf, const float4* slab,
                                     int c0_, int c1_, int tid)
{
    uint32_t d0 = sbase + (uint32_t)((buf*2+0)*2048 + tid*4)*4u;
    uint32_t d1 = sbase + (uint32_t)((buf*2+1)*2048 + tid*4)*4u;
    CPA16(d0, slab + (size_t)c0_*512 + tid);
    CPA16(d1, slab + (size_t)c1_*512 + tid);
    asm volatile("cp.async.commit_group;\n");
}

__device__ __forceinline__ const float* chunk_src(int c, const float* hbase,
                                                  const float* x, int s, size_t* arow)
{
    if (c<32){ *arow = HH; return hbase + c*32; }
    *arow = XROW; return x + (size_t)s*IN + (c-32)*32;
}

// gate-fused K-split persistent fp16-MMA: 128 blocks x 512 thr, 1 blk/SM.
// block: mtile=blk>>5 (64 rows), grp=blk&31 (32 h-cols), all 4 gates.
// warp: kg=w>>3, wi=w&7: mt=wi>>2 (32 rows), ho=wi&3 (8 h-cols x 4 gates).
// A smem: 16-word rows, word w at phys w^((m&7)<<1); m16n8k16 frags.
__global__ __launch_bounds__(512,1) void lstm_mma(
    const float*__restrict__ x,
    const float*__restrict__ h0,const float*__restrict__ c0,
    const float*__restrict__ bi,const float*__restrict__ bf,
    const float*__restrict__ bg,const float*__restrict__ bo,
    const float*__restrict__ Wout,const float*__restrict__ bout,
    float*__restrict__ out,int write_hc)
{
    extern __shared__ uint32_t smU[];
    float* smF = (float*)smU;
    const int tid=threadIdx.x, blk=blockIdx.x;
    const int mtile=blk>>5, grp=blk&31;
    const int m0=mtile*64;
    const int w=tid>>5, lane=tid&31;
    const int kg=w>>3, wi=w&7, mt=wi>>2, ho=wi&3;
    const int am=tid>>3, ac=(tid&7)*4;
    const int asw = ((ac>>1) ^ ((am&7)<<1));     // swizzled word within row
    const int hcol0 = grp*32 + ho*8 + 2*(lane&3);
    const int sw = (lane>>2)<<1;                  // frag-read swizzle
    uint32_t sbase = (uint32_t)__cvta_generic_to_shared(smU);
    const float4* slabF4 = (const float4*)(g_wpack + (size_t)grp*48*1024);

    float2 bias_r[4];
    bias_r[0] = *(const float2*)&bi[hcol0];
    bias_r[1] = *(const float2*)&bf[hcol0];
    bias_r[2] = *(const float2*)&bg[hcol0];
    bias_r[3] = *(const float2*)&bo[hcol0];

    float creg[8];
    unsigned ls=0;

    for (int s=0;s<SS;s++){
        const float* hbase = (s==0)?h0:g_hbuf[s&1];
        float* hnext = g_hbuf[(s+1)&1];

        if (s>0 && w<2) out_proj_warp(g_hbuf[s&1], blk*2+w, s-1, Wout, bout, out);

        float acc[2][4][4];
#pragma unroll
        for (int ms=0;ms<2;ms++)
#pragma unroll
            for (int g4=0;g4<4;g4++)
#pragma unroll
                for (int q=0;q<4;q++) acc[ms][g4][q]=0.f;

        // prologue: stage pair 0 (chunks 0 and NIT) into buf 0
        cpB2(sbase, 0, slabF4, 0, NIT, tid);
#pragma unroll
        for (int kgc=0;kgc<2;kgc++){
            size_t ar; const float* src = chunk_src(kgc*NIT, hbase, x, s, &ar);
            float4 v = *(const float4*)&src[(size_t)(m0+am)*ar + ac];
            uint2 u; u.x = pkh2(v.x,v.y); u.y = pkh2(v.z,v.w);
            *(uint2*)&smU[AOFFW + kgc*1024 + am*16 + asw] = u;
        }
        asm volatile("cp.async.wait_group 0;\n");
        __syncthreads();

        for (int i=0;i<NIT;i++){
            float4 va, vb;
            const bool more = (i+1 < NIT);
            if (more){
                cpB2(sbase, (i+1)&1, slabF4, i+1, NIT+i+1, tid);
                size_t ar0, ar1;
                const float* s0 = chunk_src(i+1, hbase, x, s, &ar0);
                const float* s1 = chunk_src(NIT+i+1, hbase, x, s, &ar1);
                va = *(const float4*)&s0[(size_t)(m0+am)*ar0 + ac];
                vb = *(const float4*)&s1[(size_t)(m0+am)*ar1 + ac];
            }
            // MMA on buf i&1, this warp's K-half chunk (2 k16-tiles)
            {
                const int ab = AOFFW + ((i&1)*2+kg)*1024;
                const int bb = ((i&1)*2+kg)*2048;
#pragma unroll
                for (int kt=0;kt<2;kt++){
                    int w0 = (kt*8 + (lane&3)) ^ sw;
                    int w2 = (kt*8 + (lane&3) + 4) ^ sw;
                    uint32_t a[2][4];
#pragma unroll
                    for (int ms=0;ms<2;ms++){
                        int rb = ab + (mt*32+ms*16+(lane>>2))*16;
                        a[ms][0]=smU[rb + w0];      a[ms][1]=smU[rb + 128 + w0];
                        a[ms][2]=smU[rb + w2];      a[ms][3]=smU[rb + 128 + w2];
                    }
#pragma unroll
                    for (int g4=0;g4<4;g4++){
                        uint2 b = *(const uint2*)&smU[bb + (((kt*4+ho)*4+g4)*32+lane)*2];
#pragma unroll
                        for (int ms=0;ms<2;ms++){
                            asm volatile(
                                "mma.sync.aligned.m16n8k16.row.col.f32.f16.f16.f32 "
                                "{%0,%1,%2,%3},{%4,%5,%6,%7},{%8,%9},{%0,%1,%2,%3};"
                                : "+f"(acc[ms][g4][0]),"+f"(acc[ms][g4][1]),
                                  "+f"(acc[ms][g4][2]),"+f"(acc[ms][g4][3])
                                : "r"(a[ms][0]),"r"(a[ms][1]),"r"(a[ms][2]),"r"(a[ms][3]),
                                  "r"(b.x),"r"(b.y));
                        }
                    }
                }
            }
            if (more){
                uint2 u;
                u.x = pkh2(va.x,va.y); u.y = pkh2(va.z,va.w);
                *(uint2*)&smU[AOFFW + (((i+1)&1)*2+0)*1024 + am*16 + asw] = u;
                u.x = pkh2(vb.x,vb.y); u.y = pkh2(vb.z,vb.w);
                *(uint2*)&smU[AOFFW + (((i+1)&1)*2+1)*1024 + am*16 + asw] = u;
            }
            asm volatile("cp.async.wait_group 0;\n");
            __syncthreads();
        }

        // K-split merge: kg1 -> smem (lane-major, conflict-free), kg0 adds
        if (kg==1){
            int hid = wi*32+lane;
#pragma unroll
            for (int ms=0;ms<2;ms++)
#pragma unroll
                for (int g4=0;g4<4;g4++)
#pragma unroll
                    for (int q=0;q<4;q++)
                        smF[MOFF + (((ms*4+g4)*4+q)<<8) + hid] = acc[ms][g4][q];
        }
        __syncthreads();

        // epilogue (kg0): add halves + bias, LSTM update with c in registers
        if (kg==0){
            int hid = wi*32+lane;
#pragma unroll
            for (int ms=0;ms<2;ms++){
#pragma unroll
                for (int hh=0;hh<2;hh++){
                    int m = m0 + mt*32 + ms*16 + (lane>>2) + hh*8;
                    int ci = (ms*2+hh)*2;
                    float2 hv;
#pragma unroll
                    for (int cc=0;cc<2;cc++){
                        int q = hh*2+cc;
                        float pi = acc[ms][0][q] + smF[MOFF + (((ms*4+0)*4+q)<<8) + hid]
                                 + ((cc==0)?bias_r[0].x:bias_r[0].y);
                        float pf = acc[ms][1][q] + smF[MOFF + (((ms*4+1)*4+q)<<8) + hid]
                                 + ((cc==0)?bias_r[1].x:bias_r[1].y);
                        float pg = acc[ms][2][q] + smF[MOFF + (((ms*4+2)*4+q)<<8) + hid]
                                 + ((cc==0)?bias_r[2].x:bias_r[2].y);
                        float po = acc[ms][3][q] + smF[MOFF + (((ms*4+3)*4+q)<<8) + hid]
                                 + ((cc==0)?bias_r[3].x:bias_r[3].y);
                        float iv=sigf(pi), fv=sigf(pf), gv=tanhf(pg), ov=sigf(po);
                        float cp = (s==0)? c0[(size_t)m*HH + hcol0 + cc] : creg[ci+cc];
                        float cn = fv*cp + iv*gv;
                        creg[ci+cc] = cn;
                        float hn = ov*tanhf(cn);
                        if (cc==0) hv.x = hn; else hv.y = hn;
                    }
                    *(float2*)&hnext[(size_t)m*HH + hcol0] = hv;
                    if (s==SS-1 && write_hc){
                        float* oh = out + (size_t)BB*SS*OUTD;
                        float* oc = oh + BH;
                        *(float2*)&oh[(size_t)m*HH + hcol0] = hv;
                        float2 cv2; cv2.x=creg[ci]; cv2.y=creg[ci+1];
                        *(float2*)&oc[(size_t)m*HH + hcol0] = cv2;
                    }
                }
            }
        }

        gridbar(ls);   // 512 gridbars/launch -> even, replay-safe
    }

    // final out-projection for s = SS-1
    if (w<2) out_proj_warp(g_hbuf[SS&1], blk*2+w, SS-1, Wout, bout, out);
}

extern "C" void kernel_launch(void* const* d_in, const int* in_sizes, int n_in,
                              void* d_out, int out_size)
{
    const float* x   =(const float*)d_in[0];
    const float* h0  =(const float*)d_in[1];
    const float* c0  =(const float*)d_in[2];
    const float* Xi  =(const float*)d_in[3];
    const float* Hi  =(const float*)d_in[4];
    const float* bi  =(const float*)d_in[5];
    const float* Xf  =(const float*)d_in[6];
    const float* Hf  =(const float*)d_in[7];
    const float* bf  =(const float*)d_in[8];
    const float* Xg  =(const float*)d_in[9];
    const float* Hg  =(const float*)d_in[10];
    const float* bg  =(const float*)d_in[11];
    const float* Xo  =(const float*)d_in[12];
    const float* Ho  =(const float*)d_in[13];
    const float* bo  =(const float*)d_in[14];
    const float* Wout=(const float*)d_in[15];
    const float* bout=(const float*)d_in[16];
    float* out=(float*)d_out;
    const int write_hc = (out_size >= BB*SS*OUTD + 2*BH) ? 1 : 0;

    cudaFuncSetAttribute(lstm_mma, cudaFuncAttributeMaxDynamicSharedMemorySize, SMEMB);
    pack_w<<<3072,256>>>(Hi,Hf,Hg,Ho,Xi,Xf,Xg,Xo);
    lstm_mma<<<128,512,SMEMB>>>(x,h0,c0,bi,bf,bg,bo,Wout,bout,out,write_hc);
}